// round 14
// baseline (speedup 1.0000x reference)
#include <cuda_runtime.h>
#include <cuda_bf16.h>
#include <math.h>
#include <cstdint>

#define BB 64
#define SS 512
#define HH 1024
#define LL 64

__device__ float g_llh[BB];
__device__ __nv_bfloat16 g_Wth[LL * HH];      // W^T hi  [n][k]
__device__ __nv_bfloat16 g_Wtl[LL * HH];      // W^T lo  [n][k]

// ---------------------------------------------------------------------------
// mma.sync m16n8k16 bf16 (sm_80+)
// ---------------------------------------------------------------------------
__device__ __forceinline__ void mma16816(float* c, const uint32_t* a,
                                         const uint32_t* b) {
    asm volatile(
        "mma.sync.aligned.m16n8k16.row.col.f32.bf16.bf16.f32 "
        "{%0,%1,%2,%3}, {%4,%5,%6,%7}, {%8,%9}, {%0,%1,%2,%3};\n"
        : "+f"(c[0]), "+f"(c[1]), "+f"(c[2]), "+f"(c[3])
        : "r"(a[0]), "r"(a[1]), "r"(a[2]), "r"(a[3]), "r"(b[0]), "r"(b[1]));
}

__device__ __forceinline__ void cvt_hilo(float x, float y,
                                         uint32_t& hi, uint32_t& lo) {
    uint32_t h;
    asm("cvt.rn.bf16x2.f32 %0, %1, %2;" : "=r"(h) : "f"(y), "f"(x));
    float xh = __uint_as_float((h & 0xffffu) << 16);
    float yh = __uint_as_float(h & 0xffff0000u);
    float xr = x - xh, yr = y - yh;
    asm("cvt.rn.bf16x2.f32 %0, %1, %2;" : "=r"(lo) : "f"(yr), "f"(xr));
    hi = h;
}

__device__ __forceinline__ unsigned short bfbits(float x) {
    __nv_bfloat16 h = __float2bfloat16_rn(x);
    return *reinterpret_cast<unsigned short*>(&h);
}
__device__ __forceinline__ float bf2f(unsigned short u) {
    __nv_bfloat16 h = *reinterpret_cast<__nv_bfloat16*>(&u);
    return __bfloat162float(h);
}

// ---------------------------------------------------------------------------
// prep: Wt_hi[n][k] = bf16(W[k][n]); Wt_lo = bf16(residual)
// ---------------------------------------------------------------------------
__global__ __launch_bounds__(256) void prep_kernel(const float* __restrict__ W) {
    int idx = blockIdx.x * 256 + threadIdx.x;     // 0 .. 65535
    int n = idx >> 10, k = idx & 1023;
    float v = W[k * LL + n];
    unsigned short h = bfbits(v);
    float r = v - bf2f(h);
    g_Wth[n * HH + k] = *reinterpret_cast<__nv_bfloat16*>(&h);
    unsigned short l = bfbits(r);
    g_Wtl[n * HH + k] = *reinterpret_cast<__nv_bfloat16*>(&l);
}

// ---------------------------------------------------------------------------
// GEMM via mma.sync (R13, measured-good). Epilogue: em only (no E scratch).
// ---------------------------------------------------------------------------
#define KPAD 136

__global__ __launch_bounds__(128) void gemm_kernel(
    const float* __restrict__ hs, const float* __restrict__ bias,
    float* __restrict__ out_em)
{
    __shared__ __align__(16) __nv_bfloat16 Bh_s[LL * KPAD];
    __shared__ __align__(16) __nv_bfloat16 Bl_s[LL * KPAD];

    const int tid = threadIdx.x;
    const int wid = tid >> 5;
    const int lane = tid & 31;
    const int gid = lane >> 2;
    const int tig = lane & 3;
    const int m0 = blockIdx.x * 128;

    float acc[2][8][4];
#pragma unroll
    for (int mf = 0; mf < 2; mf++)
#pragma unroll
        for (int nf = 0; nf < 8; nf++)
#pragma unroll
            for (int i = 0; i < 4; i++) acc[mf][nf][i] = 0.f;

    for (int c = 0; c < 8; c++) {
        __syncthreads();
#pragma unroll
        for (int p = 0; p < 8; p++) {
            int idx = tid + p * 128;
            int n = idx >> 4, u = idx & 15;
            *(uint4*)((char*)Bh_s + n * (KPAD * 2) + u * 16) =
                *(const uint4*)((const char*)g_Wth + (size_t)n * 2048 + c * 256 + u * 16);
            *(uint4*)((char*)Bl_s + n * (KPAD * 2) + u * 16) =
                *(const uint4*)((const char*)g_Wtl + (size_t)n * 2048 + c * 256 + u * 16);
        }
        __syncthreads();

#pragma unroll
        for (int ks = 0; ks < 8; ks++) {
            const int k0 = c * 128 + ks * 16 + tig * 2;
            uint32_t ah[2][4], al[2][4];
#pragma unroll
            for (int mf = 0; mf < 2; mf++) {
                int r0 = m0 + wid * 32 + mf * 16 + gid;
                const float* base = hs + (size_t)r0 * HH;
                float2 v00 = *(const float2*)(base + k0);
                float2 v01 = *(const float2*)(base + k0 + 8);
                float2 v10 = *(const float2*)(base + 8 * HH + k0);
                float2 v11 = *(const float2*)(base + 8 * HH + k0 + 8);
                cvt_hilo(v00.x, v00.y, ah[mf][0], al[mf][0]);
                cvt_hilo(v10.x, v10.y, ah[mf][1], al[mf][1]);
                cvt_hilo(v01.x, v01.y, ah[mf][2], al[mf][2]);
                cvt_hilo(v11.x, v11.y, ah[mf][3], al[mf][3]);
            }
            uint32_t bh[8][2], bl[8][2];
            const int kk = ks * 16 + tig * 2;
#pragma unroll
            for (int nf = 0; nf < 8; nf++) {
                int n = nf * 8 + gid;
                int off0 = (n * KPAD + kk) * 2;
                bh[nf][0] = *(const uint32_t*)((const char*)Bh_s + off0);
                bh[nf][1] = *(const uint32_t*)((const char*)Bh_s + off0 + 16);
                bl[nf][0] = *(const uint32_t*)((const char*)Bl_s + off0);
                bl[nf][1] = *(const uint32_t*)((const char*)Bl_s + off0 + 16);
            }
#pragma unroll
            for (int mf = 0; mf < 2; mf++)
#pragma unroll
                for (int nf = 0; nf < 8; nf++) {
                    mma16816(acc[mf][nf], ah[mf], bh[nf]);
                    mma16816(acc[mf][nf], ah[mf], bl[nf]);
                    mma16816(acc[mf][nf], al[mf], bh[nf]);
                }
        }
    }

#pragma unroll
    for (int mf = 0; mf < 2; mf++) {
        int r0 = m0 + wid * 32 + mf * 16 + gid;
#pragma unroll
        for (int nf = 0; nf < 8; nf++) {
            int col = nf * 8 + tig * 2;
            float b0v = bias[col], b1v = bias[col + 1];
            size_t p0 = (size_t)r0 * LL + col;
            size_t p1 = (size_t)(r0 + 8) * LL + col;
            out_em[p0] = acc[mf][nf][0] + b0v;
            out_em[p0 + 1] = acc[mf][nf][1] + b1v;
            out_em[p1] = acc[mf][nf][2] + b0v;
            out_em[p1 + 1] = acc[mf][nf][3] + b1v;
        }
    }
}

// ---------------------------------------------------------------------------
// CRF bidirectional: 64 blocks x 128 threads.
//   warps 0-1 (j=tid):      forward  alpha scan, t = 1..h
//   warps 2-3 (j=tid-64):   backward beta scan,  t = len-2..h
// Z = sum_j alpha_j(h) * beta_j(h). Renorm by elem 0 every 8 steps per side.
// Emissions read from global with 2-step register prefetch, exp on use.
// ---------------------------------------------------------------------------
union F4U { float4 v; float f[4]; unsigned long long u[2]; };
__device__ __forceinline__ void ffma2(unsigned long long& d,
                                      unsigned long long a, unsigned long long b) {
    asm("fma.rn.f32x2 %0, %1, %2, %0;" : "+l"(d) : "l"(a), "l"(b));
}
__device__ __forceinline__ float lo2(unsigned long long x) {
    return __uint_as_float((unsigned)(x & 0xffffffffull));
}
__device__ __forceinline__ float hi2(unsigned long long x) {
    return __uint_as_float((unsigned)(x >> 32));
}
__device__ __forceinline__ unsigned long long pack2(float a, float b) {
    return (unsigned long long)__float_as_uint(a) |
           ((unsigned long long)__float_as_uint(b) << 32);
}
__device__ __forceinline__ int tag_of(int x) {
    int t = (x == -100) ? 0 : x;
    return max(0, min(LL - 1, t));
}

__device__ __forceinline__ float gemv64(const float* U,
                                        const unsigned long long* P2) {
    unsigned long long a0 = 0ull, a1 = 0ull, a2 = 0ull, a3 = 0ull;
#pragma unroll
    for (int q4 = 0; q4 < 16; q4 += 2) {
        F4U ua, ub;
        ua.v = *(const float4*)&U[q4 * 4];
        ub.v = *(const float4*)&U[q4 * 4 + 4];
        ffma2(a0, ua.u[0], P2[2 * q4 + 0]);
        ffma2(a1, ua.u[1], P2[2 * q4 + 1]);
        ffma2(a2, ub.u[0], P2[2 * q4 + 2]);
        ffma2(a3, ub.u[1], P2[2 * q4 + 3]);
    }
    return (lo2(a0) + hi2(a0)) + (lo2(a1) + hi2(a1)) +
           (lo2(a2) + hi2(a2)) + (lo2(a3) + hi2(a3));
}

__global__ __launch_bounds__(128) void crf_kernel(
    const float* __restrict__ em_all,   // = d_out + 1
    const int* __restrict__ mask,
    const int* __restrict__ labels,
    const float* __restrict__ start_t,
    const float* __restrict__ end_t,
    const float* __restrict__ trans)
{
    const int b = blockIdx.x;
    const int tid = threadIdx.x;
    const bool is_f = tid < 64;
    const int j = tid & 63;

    const float* em = em_all + (size_t)b * (SS * LL);
    const int* msk = mask + b * SS;
    const int* lab = labels + (size_t)b * SS;

    __shared__ __align__(16) float uF[2][64];
    __shared__ __align__(16) float uB[2][64];
    __shared__ __align__(16) float bF[64];
    __shared__ float red[128];
    __shared__ int len_sh;
    __shared__ float num_sh, shF_sh, shB_sh;

    // ---- length ----
    int cnt = 0;
    for (int t = tid; t < SS; t += 128) cnt += msk[t];
    red[tid] = (float)cnt;
    __syncthreads();
#pragma unroll
    for (int s = 64; s > 0; s >>= 1) {
        if (tid < s) red[tid] += red[tid + s];
        __syncthreads();
    }
    if (tid == 0) len_sh = max(1, min(SS, (int)(red[0] + 0.5f)));
    __syncthreads();
    const int len = len_sh;

    // ---- numerator ----
    float nsum = 0.f;
    for (int t = 1 + tid; t < len; t += 128) {
        int tp = tag_of(lab[t - 1]);
        int tc = tag_of(lab[t]);
        nsum += trans[tp * LL + tc] + em[t * LL + tc];
    }
    __syncthreads();
    red[tid] = nsum;
    __syncthreads();
#pragma unroll
    for (int s = 64; s > 0; s >>= 1) {
        if (tid < s) red[tid] += red[tid + s];
        __syncthreads();
    }
    if (tid == 0) {
        int t0 = tag_of(lab[0]);
        int tl = tag_of(lab[len - 1]);
        num_sh = start_t[t0] + em[t0] + red[0] + end_t[tl];
    }

    const int h = (len - 1) >> 1;
    const int nsteps = len - 1 - h;

    // ---- P registers: forward = columns of P, backward = rows ----
    unsigned long long P2[32];
    if (is_f) {
#pragma unroll
        for (int q = 0; q < 32; q++)
            P2[q] = pack2(__expf(trans[(2 * q) * LL + j]),
                          __expf(trans[(2 * q + 1) * LL + j]));
    } else {
#pragma unroll
        for (int q = 0; q < 32; q++)
            P2[q] = pack2(__expf(trans[j * LL + 2 * q]),
                          __expf(trans[j * LL + 2 * q + 1]));
    }

    // ---- init ----
    float logshift = 0.f;
    if (is_f) {
        uF[0][j] = __expf(start_t[j] + em[j]);
    } else {
        if (len > 1)
            uB[0][j] = __expf(em[(size_t)(len - 1) * LL + j] + end_t[j]);
        else
            bF[j] = __expf(end_t[j]);
    }

    // ---- emission prefetch (2 ahead) ----
    float emA = 0.f, emBv = 0.f;
    if (is_f) {
        if (h >= 1) emA = em[(size_t)1 * LL + j];
        if (h >= 2) emBv = em[(size_t)2 * LL + j];
    } else {
        if (nsteps >= 1) emA = em[(size_t)(len - 2) * LL + j];
        if (nsteps >= 2) emBv = em[(size_t)(len - 3) * LL + j];
    }

    for (int i = 1; i <= nsteps; i++) {
        __syncthreads();    // previous writes visible to both sides
        const int pb = (i - 1) & 1, cb = i & 1;
        if (is_f) {
            if (i <= h) {
                float u0 = uF[pb][0];
                float r = gemv64(uF[pb], P2);
                float e = __expf(emA);
                emA = emBv;
                if (i + 2 <= h) emBv = em[(size_t)(i + 2) * LL + j];
                float wn = r * e;
                if ((i & 7) == 0) {
                    wn *= __frcp_rn(u0);
                    logshift += __logf(u0);
                }
                uF[cb][j] = wn;
            }
        } else {
            float v0 = uB[pb][0];
            float beta = gemv64(uB[pb], P2);
            if ((i & 7) == 0) {
                beta *= __frcp_rn(v0);
                logshift += __logf(v0);
            }
            int t = len - 1 - i;
            if (t > h) {
                uB[cb][j] = beta * __expf(emA);
            } else {
                bF[j] = beta;       // final beta(h), raw (no emission at h)
            }
            emA = emBv;
            if (i + 2 <= nsteps) emBv = em[(size_t)(len - 1 - (i + 2)) * LL + j];
        }
    }
    __syncthreads();

    if (tid == 0) shF_sh = logshift;
    if (tid == 64) shB_sh = logshift;
    red[tid] = is_f ? uF[h & 1][j] * bF[j] : 0.f;
    __syncthreads();
#pragma unroll
    for (int s = 64; s > 0; s >>= 1) {
        if (tid < s) red[tid] += red[tid + s];
        __syncthreads();
    }
    if (tid == 0) {
        float log_z = __logf(red[0]) + shF_sh + shB_sh;
        g_llh[b] = num_sh - log_z;
    }
}

// ---------------------------------------------------------------------------
__global__ void loss_kernel(float* __restrict__ out) {
    int t = threadIdx.x;
    float v = g_llh[t] + g_llh[t + 32];
#pragma unroll
    for (int o = 16; o > 0; o >>= 1) v += __shfl_down_sync(0xffffffffu, v, o);
    if (t == 0) out[0] = -v * (1.0f / BB);
}

// ---------------------------------------------------------------------------
extern "C" void kernel_launch(void* const* d_in, const int* in_sizes, int n_in,
                              void* d_out, int out_size)
{
    const float* hs      = (const float*)d_in[0];
    const int* mask      = (const int*)d_in[1];
    const int* labels    = (const int*)d_in[2];
    const float* W       = (const float*)d_in[3];
    const float* bias    = (const float*)d_in[4];
    const float* start_t = (const float*)d_in[5];
    const float* end_t   = (const float*)d_in[6];
    const float* trans   = (const float*)d_in[7];
    float* out = (float*)d_out;    // out[0]=loss, out[1..]=emissions

    prep_kernel<<<256, 256>>>(W);
    gemm_kernel<<<256, 128>>>(hs, bias, out + 1);
    crf_kernel<<<BB, 128>>>(out + 1, mask, labels, start_t, end_t, trans);
    loss_kernel<<<1, 32>>>(out);
}

// round 17
// speedup vs baseline: 1.4387x; 1.4387x over previous
#include <cuda_runtime.h>
#include <cuda_bf16.h>
#include <math.h>
#include <cstdint>

#define BB 64
#define SS 512
#define HH 1024
#define LL 64
#define NEM (BB * SS * LL)

__device__ float g_E[NEM];                    // exp(emissions)
__device__ float g_llh[BB];
__device__ __nv_bfloat16 g_Wth[LL * HH];      // W^T hi  [n][k]
__device__ __nv_bfloat16 g_Wtl[LL * HH];      // W^T lo  [n][k]

// ---------------------------------------------------------------------------
// mma.sync m16n8k16 bf16 (sm_80+)
// ---------------------------------------------------------------------------
__device__ __forceinline__ void mma16816(float* c, const uint32_t* a,
                                         const uint32_t* b) {
    asm volatile(
        "mma.sync.aligned.m16n8k16.row.col.f32.bf16.bf16.f32 "
        "{%0,%1,%2,%3}, {%4,%5,%6,%7}, {%8,%9}, {%0,%1,%2,%3};\n"
        : "+f"(c[0]), "+f"(c[1]), "+f"(c[2]), "+f"(c[3])
        : "r"(a[0]), "r"(a[1]), "r"(a[2]), "r"(a[3]), "r"(b[0]), "r"(b[1]));
}

__device__ __forceinline__ void cvt_hilo(float x, float y,
                                         uint32_t& hi, uint32_t& lo) {
    uint32_t h;
    asm("cvt.rn.bf16x2.f32 %0, %1, %2;" : "=r"(h) : "f"(y), "f"(x));
    float xh = __uint_as_float((h & 0xffffu) << 16);
    float yh = __uint_as_float(h & 0xffff0000u);
    float xr = x - xh, yr = y - yh;
    asm("cvt.rn.bf16x2.f32 %0, %1, %2;" : "=r"(lo) : "f"(yr), "f"(xr));
    hi = h;
}

__device__ __forceinline__ unsigned short bfbits(float x) {
    __nv_bfloat16 h = __float2bfloat16_rn(x);
    return *reinterpret_cast<unsigned short*>(&h);
}
__device__ __forceinline__ float bf2f(unsigned short u) {
    __nv_bfloat16 h = *reinterpret_cast<__nv_bfloat16*>(&u);
    return __bfloat162float(h);
}

// ---------------------------------------------------------------------------
// prep: Wt_hi[n][k] = bf16(W[k][n]); Wt_lo = bf16(residual)
// ---------------------------------------------------------------------------
__global__ __launch_bounds__(256) void prep_kernel(const float* __restrict__ W) {
    int idx = blockIdx.x * 256 + threadIdx.x;
    int n = idx >> 10, k = idx & 1023;
    float v = W[k * LL + n];
    unsigned short h = bfbits(v);
    float r = v - bf2f(h);
    g_Wth[n * HH + k] = *reinterpret_cast<__nv_bfloat16*>(&h);
    unsigned short l = bfbits(r);
    g_Wtl[n * HH + k] = *reinterpret_cast<__nv_bfloat16*>(&l);
}

// ---------------------------------------------------------------------------
// GEMM via mma.sync: m-tile 64 (1 m-frag per warp), 128 threads, grid 512.
// Per k16-step per warp: 1 A-frag (hi/lo split in regs), 8 B-frags (smem),
// 24 HMMA (Ahi*Bhi, Ahi*Blo, Alo*Bhi). Writes em and E=exp(em).
// ---------------------------------------------------------------------------
#define KPAD 136

__global__ __launch_bounds__(128) void gemm_kernel(
    const float* __restrict__ hs, const float* __restrict__ bias,
    float* __restrict__ out_em, float* __restrict__ Eo)
{
    __shared__ __align__(16) __nv_bfloat16 Bh_s[LL * KPAD];
    __shared__ __align__(16) __nv_bfloat16 Bl_s[LL * KPAD];

    const int tid = threadIdx.x;
    const int wid = tid >> 5;
    const int lane = tid & 31;
    const int gid = lane >> 2;
    const int tig = lane & 3;
    const int m0 = blockIdx.x * 64;

    float acc[8][4];
#pragma unroll
    for (int nf = 0; nf < 8; nf++)
#pragma unroll
        for (int i = 0; i < 4; i++) acc[nf][i] = 0.f;

    for (int c = 0; c < 8; c++) {
        __syncthreads();
#pragma unroll
        for (int p = 0; p < 8; p++) {
            int idx = tid + p * 128;
            int n = idx >> 4, u = idx & 15;
            *(uint4*)((char*)Bh_s + n * (KPAD * 2) + u * 16) =
                *(const uint4*)((const char*)g_Wth + (size_t)n * 2048 + c * 256 + u * 16);
            *(uint4*)((char*)Bl_s + n * (KPAD * 2) + u * 16) =
                *(const uint4*)((const char*)g_Wtl + (size_t)n * 2048 + c * 256 + u * 16);
        }
        __syncthreads();

#pragma unroll
        for (int ks = 0; ks < 8; ks++) {
            const int k0 = c * 128 + ks * 16 + tig * 2;
            // ---- A fragment: rows (r0, r0+8), cols (k0, k0+8) ----
            uint32_t ah[4], al[4];
            {
                int r0 = m0 + wid * 16 + gid;
                const float* base = hs + (size_t)r0 * HH;
                float2 v00 = *(const float2*)(base + k0);
                float2 v01 = *(const float2*)(base + k0 + 8);
                float2 v10 = *(const float2*)(base + 8 * HH + k0);
                float2 v11 = *(const float2*)(base + 8 * HH + k0 + 8);
                cvt_hilo(v00.x, v00.y, ah[0], al[0]);
                cvt_hilo(v10.x, v10.y, ah[1], al[1]);
                cvt_hilo(v01.x, v01.y, ah[2], al[2]);
                cvt_hilo(v11.x, v11.y, ah[3], al[3]);
            }
            // ---- B fragments from smem ----
            uint32_t bh[8][2], bl[8][2];
            const int kk = ks * 16 + tig * 2;
#pragma unroll
            for (int nf = 0; nf < 8; nf++) {
                int n = nf * 8 + gid;
                int off0 = (n * KPAD + kk) * 2;
                bh[nf][0] = *(const uint32_t*)((const char*)Bh_s + off0);
                bh[nf][1] = *(const uint32_t*)((const char*)Bh_s + off0 + 16);
                bl[nf][0] = *(const uint32_t*)((const char*)Bl_s + off0);
                bl[nf][1] = *(const uint32_t*)((const char*)Bl_s + off0 + 16);
            }
            // ---- 24 HMMA ----
#pragma unroll
            for (int nf = 0; nf < 8; nf++) {
                mma16816(acc[nf], ah, bh[nf]);
                mma16816(acc[nf], ah, bl[nf]);
                mma16816(acc[nf], al, bh[nf]);
            }
        }
    }

    // ---- epilogue ----
    {
        int r0 = m0 + wid * 16 + gid;
#pragma unroll
        for (int nf = 0; nf < 8; nf++) {
            int col = nf * 8 + tig * 2;
            float b0v = bias[col], b1v = bias[col + 1];
            float e0 = acc[nf][0] + b0v;
            float e1 = acc[nf][1] + b1v;
            float e2 = acc[nf][2] + b0v;
            float e3 = acc[nf][3] + b1v;
            size_t p0 = (size_t)r0 * LL + col;
            size_t p1 = (size_t)(r0 + 8) * LL + col;
            out_em[p0] = e0; out_em[p0 + 1] = e1;
            out_em[p1] = e2; out_em[p1 + 1] = e3;
            *(float2*)&Eo[p0] = make_float2(__expf(e0), __expf(e1));
            *(float2*)&Eo[p1] = make_float2(__expf(e2), __expf(e3));
        }
    }
}

// ---------------------------------------------------------------------------
// CRF (R13 verbatim, measured-good ~102us): 64 blocks x 64 threads,
// linear-space forward scan, P=exp(trans) in regs, renorm every 8 steps,
// E double-buffered in smem (32-step chunks).
// ---------------------------------------------------------------------------
union F4U { float4 v; float f[4]; unsigned long long u[2]; };
__device__ __forceinline__ void ffma2(unsigned long long& d,
                                      unsigned long long a, unsigned long long b) {
    asm("fma.rn.f32x2 %0, %1, %2, %0;" : "+l"(d) : "l"(a), "l"(b));
}
__device__ __forceinline__ float lo2(unsigned long long x) {
    return __uint_as_float((unsigned)(x & 0xffffffffull));
}
__device__ __forceinline__ float hi2(unsigned long long x) {
    return __uint_as_float((unsigned)(x >> 32));
}
__device__ __forceinline__ unsigned long long pack2(float a, float b) {
    return (unsigned long long)__float_as_uint(a) |
           ((unsigned long long)__float_as_uint(b) << 32);
}
__device__ __forceinline__ int tag_of(int x) {
    int t = (x == -100) ? 0 : x;
    return max(0, min(LL - 1, t));
}

__global__ __launch_bounds__(64) void crf_kernel(
    const float* __restrict__ em_all,   // = d_out + 1 (raw, for numerator)
    const float* __restrict__ E_all,    // g_E
    const int* __restrict__ mask,
    const int* __restrict__ labels,
    const float* __restrict__ start_t,
    const float* __restrict__ end_t,
    const float* __restrict__ trans)
{
    const int b = blockIdx.x;
    const int j = threadIdx.x;

    const float* em = em_all + (size_t)b * (SS * LL);
    const float* Ee = E_all + (size_t)b * (SS * LL);
    const int* msk = mask + b * SS;
    const int* lab = labels + (size_t)b * SS;

    __shared__ __align__(16) float4 u_sh[2][16];
    __shared__ __align__(16) float4 Esm[2][512];
    __shared__ float red[64];
    __shared__ int len_sh;
    __shared__ float num_sh;

    int cnt = 0;
    for (int t = j; t < SS; t += 64) cnt += msk[t];
    red[j] = (float)cnt;
    __syncthreads();
#pragma unroll
    for (int s = 32; s > 0; s >>= 1) {
        if (j < s) red[j] += red[j + s];
        __syncthreads();
    }
    if (j == 0) len_sh = max(1, min(SS, (int)(red[0] + 0.5f)));
    __syncthreads();
    const int len = len_sh;

    float nsum = 0.f;
    for (int t = 1 + j; t < len; t += 64) {
        int tp = tag_of(lab[t - 1]);
        int tc = tag_of(lab[t]);
        nsum += trans[tp * LL + tc] + em[t * LL + tc];
    }
    __syncthreads();
    red[j] = nsum;
    __syncthreads();
#pragma unroll
    for (int s = 32; s > 0; s >>= 1) {
        if (j < s) red[j] += red[j + s];
        __syncthreads();
    }
    if (j == 0) {
        int t0 = tag_of(lab[0]);
        int tl = tag_of(lab[len - 1]);
        num_sh = start_t[t0] + em[t0] + red[0] + end_t[tl];
    }

    unsigned long long P2[32];
#pragma unroll
    for (int q = 0; q < 32; q++)
        P2[q] = pack2(__expf(trans[(2 * q) * LL + j]),
                      __expf(trans[(2 * q + 1) * LL + j]));

#pragma unroll
    for (int p = 0; p < 8; p++) {
        int idx = p * 64 + j;
        Esm[0][idx] = *(const float4*)&Ee[(size_t)idx * 4];
    }
    __syncthreads();

    float w = __expf(start_t[j]) * ((const float*)Esm[0])[j];
    ((float*)u_sh[0])[j] = w;
    float logshift = 0.f;

    const int nchunks = (len + 31) >> 5;
    for (int ch = 0; ch < nchunks; ch++) {
        if (ch + 1 < nchunks) {
            int t0n = (ch + 1) << 5;
            int nq = min(512, (len - t0n) * 16);
#pragma unroll
            for (int p = 0; p < 8; p++) {
                int idx = p * 64 + j;
                if (idx < nq)
                    Esm[(ch + 1) & 1][idx] =
                        *(const float4*)&Ee[(size_t)t0n * 64 + (size_t)idx * 4];
            }
        }
        const float* Ep = (const float*)Esm[ch & 1];
        int tA = (ch == 0) ? 1 : (ch << 5);
        int tB = min(len, (ch + 1) << 5);

        for (int t = tA; t < tB; t++) {
            __syncthreads();
            const float4* U = u_sh[(t - 1) & 1];
            float u0 = ((const float*)U)[0];

            unsigned long long a0 = 0ull, a1 = 0ull, a2 = 0ull, a3 = 0ull;
#pragma unroll
            for (int q4 = 0; q4 < 16; q4 += 2) {
                F4U ua, ub;
                ua.v = U[q4];
                ub.v = U[q4 + 1];
                ffma2(a0, ua.u[0], P2[2 * q4 + 0]);
                ffma2(a1, ua.u[1], P2[2 * q4 + 1]);
                ffma2(a2, ub.u[0], P2[2 * q4 + 2]);
                ffma2(a3, ub.u[1], P2[2 * q4 + 3]);
            }
            float r = (lo2(a0) + hi2(a0)) + (lo2(a1) + hi2(a1)) +
                      (lo2(a2) + hi2(a2)) + (lo2(a3) + hi2(a3));
            float e = Ep[((t & 31) << 6) + j];
            float wn = r * e;
            if ((t & 7) == 0) {
                wn *= __frcp_rn(u0);
                logshift += __logf(u0);
            }
            w = wn;
            ((float*)u_sh[t & 1])[j] = w;
        }
        __syncthreads();
    }

    red[j] = w * __expf(end_t[j]);
    __syncthreads();
#pragma unroll
    for (int s = 32; s > 0; s >>= 1) {
        if (j < s) red[j] += red[j + s];
        __syncthreads();
    }
    if (j == 0) {
        float log_z = __logf(red[0]) + logshift;
        g_llh[b] = num_sh - log_z;
    }
}

// ---------------------------------------------------------------------------
__global__ void loss_kernel(float* __restrict__ out) {
    int t = threadIdx.x;
    float v = g_llh[t] + g_llh[t + 32];
#pragma unroll
    for (int o = 16; o > 0; o >>= 1) v += __shfl_down_sync(0xffffffffu, v, o);
    if (t == 0) out[0] = -v * (1.0f / BB);
}

// ---------------------------------------------------------------------------
extern "C" void kernel_launch(void* const* d_in, const int* in_sizes, int n_in,
                              void* d_out, int out_size)
{
    const float* hs      = (const float*)d_in[0];
    const int* mask      = (const int*)d_in[1];
    const int* labels    = (const int*)d_in[2];
    const float* W       = (const float*)d_in[3];
    const float* bias    = (const float*)d_in[4];
    const float* start_t = (const float*)d_in[5];
    const float* end_t   = (const float*)d_in[6];
    const float* trans   = (const float*)d_in[7];
    float* out = (float*)d_out;    // out[0]=loss, out[1..]=emissions

    float* E_scratch = nullptr;
    cudaGetSymbolAddress((void**)&E_scratch, g_E);

    prep_kernel<<<256, 256>>>(W);
    gemm_kernel<<<512, 128>>>(hs, bias, out + 1, E_scratch);
    crf_kernel<<<BB, 64>>>(out + 1, E_scratch, mask, labels,
                           start_t, end_t, trans);
    loss_kernel<<<1, 32>>>(out);
}